// round 2
// baseline (speedup 1.0000x reference)
#include <cuda_runtime.h>

// Problem constants
#define Bn   4
#define CHI  256
#define CHO  256
#define Hd   96
#define Wd   96
#define Kt   9
#define HW   (Hd*Wd)          // 9216
#define Mpx  (Bn*HW)          // 36864
#define KD   (CHI*Kt)         // 2304
#define BN_EPS 1e-5f

// Precomputed bilinear tap: 4 clamped gather offsets (within one channel plane)
// + 4 corner weights (validity and sigmoid(mask) folded in).
struct __align__(16) TapParam {
    int   o00, o01, o10, o11;
    float w00, w01, w10, w11;
};

// Scratch (device globals: allocation-guard-safe)
__device__ TapParam g_params[Bn * Kt * HW];              // ~10.6 MB
__device__ float    g_cols[(size_t)KD * Mpx];            // ~340 MB
__device__ float    g_stats[2 * CHO];                    // mean, rstd

// ---------------------------------------------------------------------------
// Kernel 1: offset conv (256->27, 3x3, pad 1) + fold into TapParams.
// One thread per output pixel, 27 accumulators, weights staged in smem.
// ---------------------------------------------------------------------------
#define OC  27
#define OCP 32   // padded stride for LDS.128-friendly rows

__global__ void __launch_bounds__(128) k_offset(
    const float* __restrict__ x,
    const float* __restrict__ w_off,
    const float* __restrict__ b_off)
{
    __shared__ float ws[32 * 9 * OCP];   // 36 KB: 32-channel chunk of weights
    int p  = blockIdx.x * 128 + threadIdx.x;   // grid.x = Mpx/128 = 288
    int b  = p / HW, hw = p % HW;
    int h  = hw / Wd, w = hw % Wd;

    float acc[OC];
#pragma unroll
    for (int i = 0; i < OC; i++) acc[i] = 0.f;

    for (int c0 = 0; c0 < CHI; c0 += 32) {
        __syncthreads();
        for (int i = threadIdx.x; i < 32 * 9 * OC; i += 128) {
            int oc = i % OC;
            int ct = i / OC;                 // cc*9 + t
            ws[ct * OCP + oc] = w_off[(oc * CHI + c0 + ct / 9) * 9 + (ct % 9)];
        }
        __syncthreads();

        const float* xb = x + ((size_t)b * CHI + c0) * HW;
        for (int cc = 0; cc < 32; cc++) {
            const float* xc = xb + cc * HW;
#pragma unroll
            for (int ty = 0; ty < 3; ty++) {
                int y = h + ty - 1;
                bool yv = ((unsigned)y < (unsigned)Hd);
#pragma unroll
                for (int tx = 0; tx < 3; tx++) {
                    int xx = w + tx - 1;
                    float xv = (yv && (unsigned)xx < (unsigned)Wd) ? xc[y * Wd + xx] : 0.f;
                    const float* wr = &ws[(cc * 9 + ty * 3 + tx) * OCP];
#pragma unroll
                    for (int oc = 0; oc < OC; oc++) acc[oc] += wr[oc] * xv;
                }
            }
        }
    }

    // Epilogue: build TapParams for the 9 taps of this pixel.
#pragma unroll
    for (int k = 0; k < Kt; k++) {
        float dy = acc[2 * k]     + b_off[2 * k];
        float dx = acc[2 * k + 1] + b_off[2 * k + 1];
        float mz = acc[18 + k]    + b_off[18 + k];
        float m  = 1.f / (1.f + expf(-mz));

        float py = dy + (float)(h + k / 3 - 1);
        float px = dx + (float)(w + k % 3 - 1);
        float fy = floorf(py), fx = floorf(px);
        float ly = py - fy,    lx = px - fx;
        int y0 = (int)fy, x0 = (int)fx, y1 = y0 + 1, x1 = x0 + 1;

        float vy0 = ((unsigned)y0 < (unsigned)Hd) ? 1.f : 0.f;
        float vy1 = ((unsigned)y1 < (unsigned)Hd) ? 1.f : 0.f;
        float vx0 = ((unsigned)x0 < (unsigned)Wd) ? 1.f : 0.f;
        float vx1 = ((unsigned)x1 < (unsigned)Wd) ? 1.f : 0.f;

        int y0c = min(max(y0, 0), Hd - 1), y1c = min(max(y1, 0), Hd - 1);
        int x0c = min(max(x0, 0), Wd - 1), x1c = min(max(x1, 0), Wd - 1);

        TapParam tp;
        tp.o00 = y0c * Wd + x0c;  tp.o01 = y0c * Wd + x1c;
        tp.o10 = y1c * Wd + x0c;  tp.o11 = y1c * Wd + x1c;
        tp.w00 = (1.f - ly) * (1.f - lx) * vy0 * vx0 * m;
        tp.w01 = (1.f - ly) * lx         * vy0 * vx1 * m;
        tp.w10 = ly * (1.f - lx)         * vy1 * vx0 * m;
        tp.w11 = ly * lx                 * vy1 * vx1 * m;
        g_params[(b * Kt + k) * HW + hw] = tp;
    }
}

// ---------------------------------------------------------------------------
// Kernel 2: deformable im2col. cols[(c*9+k)*Mpx + p] = masked bilinear sample.
// Thread = (pixel, 16-channel chunk); k-outer keeps TapParam in registers.
// ---------------------------------------------------------------------------
#define CCH 16

__global__ void __launch_bounds__(256) k_cols(const float* __restrict__ x)
{
    int p  = blockIdx.x * 256 + threadIdx.x;   // grid.x = Mpx/256 = 144
    int c0 = blockIdx.y * CCH;                 // grid.y = CHI/CCH = 16
    int b  = p / HW, hw = p % HW;
    const float* xb = x + ((size_t)b * CHI + c0) * HW;

#pragma unroll 1
    for (int k = 0; k < Kt; k++) {
        TapParam tp = g_params[(b * Kt + k) * HW + hw];
        float* dst = g_cols + ((size_t)(c0 * Kt + k)) * Mpx + p;
        const float* xc = xb;
#pragma unroll
        for (int cc = 0; cc < CCH; cc++) {
            float v = tp.w00 * xc[tp.o00] + tp.w01 * xc[tp.o01]
                    + tp.w10 * xc[tp.o10] + tp.w11 * xc[tp.o11];
            dst[(size_t)cc * Kt * Mpx] = v;
            xc += HW;
        }
    }
}

// ---------------------------------------------------------------------------
// Kernel 3: SGEMM  out[o][p] = sum_kd w_conv[o][kd] * cols[kd][p] + b_conv[o].
// 128x128 tile, BK=16, 8x8 register microtiles, 256 threads. Writes NCHW.
// ---------------------------------------------------------------------------
__global__ void __launch_bounds__(256) k_gemm(
    const float* __restrict__ A,        // w_conv as [CHO][KD]
    const float* __restrict__ bconv,
    float* __restrict__ out)
{
    __shared__ float As[16][128];       // [kk][o]
    __shared__ float Bs[16][128];       // [kk][p]

    int tid = threadIdx.x;
    int tx = tid % 16, ty = tid / 16;
    int oBase = blockIdx.y * 128;
    int pBase = blockIdx.x * 128;

    float acc[8][8];
#pragma unroll
    for (int i = 0; i < 8; i++)
#pragma unroll
        for (int j = 0; j < 8; j++) acc[i][j] = 0.f;

    int aRow = tid >> 2;            // 0..63
    int aCol = (tid & 3) * 4;       // 0,4,8,12
    int bRow = tid >> 5;            // 0..7
    int bCol = (tid & 31) * 4;

    const float* Ag = A + (size_t)(oBase + aRow) * KD + aCol;
    const float* Bg = g_cols + (size_t)bRow * Mpx + pBase + bCol;

    for (int k0 = 0; k0 < KD; k0 += 16) {
        float4 a0 = *(const float4*)(Ag + k0);
        float4 a1 = *(const float4*)(Ag + k0 + (size_t)64 * KD);
        float4 b0 = *(const float4*)(Bg + (size_t)k0 * Mpx);
        float4 b1 = *(const float4*)(Bg + (size_t)(k0 + 8) * Mpx);
        __syncthreads();
        As[aCol + 0][aRow] = a0.x; As[aCol + 1][aRow] = a0.y;
        As[aCol + 2][aRow] = a0.z; As[aCol + 3][aRow] = a0.w;
        As[aCol + 0][aRow + 64] = a1.x; As[aCol + 1][aRow + 64] = a1.y;
        As[aCol + 2][aRow + 64] = a1.z; As[aCol + 3][aRow + 64] = a1.w;
        *(float4*)&Bs[bRow][bCol]     = b0;
        *(float4*)&Bs[bRow + 8][bCol] = b1;
        __syncthreads();
#pragma unroll
        for (int kk = 0; kk < 16; kk++) {
            float af[8], bf[8];
#pragma unroll
            for (int i = 0; i < 8; i++) af[i] = As[kk][ty * 8 + i];
#pragma unroll
            for (int j = 0; j < 8; j++) bf[j] = Bs[kk][tx * 8 + j];
#pragma unroll
            for (int i = 0; i < 8; i++)
#pragma unroll
                for (int j = 0; j < 8; j++) acc[i][j] += af[i] * bf[j];
        }
    }

    // Epilogue: + bias, write NCHW (pixel tile never crosses a batch boundary:
    // 9216 % 128 == 0).
    int b = pBase / HW;
    int hwBase = pBase % HW + tx * 8;
#pragma unroll
    for (int i = 0; i < 8; i++) {
        int o = oBase + ty * 8 + i;
        float bias = bconv[o];
        float* op = out + ((size_t)b * CHO + o) * HW + hwBase;
#pragma unroll
        for (int j = 0; j < 8; j++) op[j] = acc[i][j] + bias;
    }
}

// ---------------------------------------------------------------------------
// Kernel 4: per-channel mean / rstd over (B,H,W).
// ---------------------------------------------------------------------------
__global__ void __launch_bounds__(256) k_bnstats(const float* __restrict__ out)
{
    __shared__ float ss[256], ss2[256];
    int o = blockIdx.x;
    float s = 0.f, s2 = 0.f;
    for (int i = threadIdx.x; i < Bn * HW; i += 256) {
        int b = i / HW;
        float v = out[((size_t)b * CHO + o) * HW + (i % HW)];
        s += v; s2 += v * v;
    }
    ss[threadIdx.x] = s; ss2[threadIdx.x] = s2;
    __syncthreads();
    for (int st = 128; st > 0; st >>= 1) {
        if (threadIdx.x < st) {
            ss[threadIdx.x]  += ss[threadIdx.x + st];
            ss2[threadIdx.x] += ss2[threadIdx.x + st];
        }
        __syncthreads();
    }
    if (threadIdx.x == 0) {
        float inv_n = 1.f / (float)(Bn * HW);
        float mean = ss[0] * inv_n;
        float var  = ss2[0] * inv_n - mean * mean;
        g_stats[o]       = mean;
        g_stats[CHO + o] = rsqrtf(var + BN_EPS);
    }
}

// ---------------------------------------------------------------------------
// Kernel 5: in-place BN apply + ReLU.
// ---------------------------------------------------------------------------
__global__ void __launch_bounds__(256) k_bnapply(
    float* __restrict__ out,
    const float* __restrict__ gamma,
    const float* __restrict__ beta)
{
    int i = blockIdx.x * 256 + threadIdx.x;
    int o = (i / HW) & (CHO - 1);
    float v = out[i];
    float y = gamma[o] * ((v - g_stats[o]) * g_stats[CHO + o]) + beta[o];
    out[i] = fmaxf(y, 0.f);
}

// ---------------------------------------------------------------------------
extern "C" void kernel_launch(void* const* d_in, const int* in_sizes, int n_in,
                              void* d_out, int out_size)
{
    const float* x      = (const float*)d_in[0];
    const float* w_off  = (const float*)d_in[1];
    const float* b_off  = (const float*)d_in[2];
    const float* w_conv = (const float*)d_in[3];
    const float* b_conv = (const float*)d_in[4];
    const float* gamma  = (const float*)d_in[5];
    const float* beta   = (const float*)d_in[6];
    float* out = (float*)d_out;

    k_offset<<<Mpx / 128, 128>>>(x, w_off, b_off);

    dim3 gcols(Mpx / 256, CHI / CCH);
    k_cols<<<gcols, 256>>>(x);

    dim3 ggemm(Mpx / 128, CHO / 128);
    k_gemm<<<ggemm, 256>>>(w_conv, b_conv, out);

    k_bnstats<<<CHO, 256>>>(out);
    k_bnapply<<<(size_t)Bn * CHO * HW / 256, 256>>>(out, gamma, beta);
}

// round 4
// speedup vs baseline: 1.6166x; 1.6166x over previous
#include <cuda_runtime.h>

// Problem constants
#define Bn   4
#define CHI  256
#define CHO  256
#define Hd   96
#define Wd   96
#define Kt   9
#define HW   (Hd*Wd)          // 9216
#define Mpx  (Bn*HW)          // 36864
#define KD   (CHI*Kt)         // 2304
#define BN_EPS 1e-5f

// Bilinear tap: 4 clamped offsets + 4 corner weights (validity+mask folded in)
struct __align__(16) TapParam {
    int   o00, o01, o10, o11;
    float w00, w01, w10, w11;
};

// Scratch (device globals: allocation-guard-safe)
__device__ TapParam       g_params[Bn * Kt * HW];                       // ~10.6 MB
__device__ __align__(16) unsigned short g_colsh[(size_t)Mpx * KD];      // 170 MB
__device__ __align__(16) unsigned short g_colsl[(size_t)Mpx * KD];      // 170 MB
__device__ __align__(16) unsigned short g_wh[(size_t)CHO * KD];         // 1.18 MB
__device__ __align__(16) unsigned short g_wl[(size_t)CHO * KD];
__device__ float          g_stats[2 * CHO];

// bf16 round-to-nearest-even helper
__device__ __forceinline__ unsigned bf16_rn(float v) {
    unsigned u = __float_as_uint(v);
    return (u + 0x7FFFu + ((u >> 16) & 1u)) >> 16;
}

// ---------------------------------------------------------------------------
// Kernel 1: offset conv (256->27, 3x3, pad 1) -> TapParams.
// ---------------------------------------------------------------------------
#define OC  27
#define OCP 32

__global__ void __launch_bounds__(128) k_offset(
    const float* __restrict__ x,
    const float* __restrict__ w_off,
    const float* __restrict__ b_off)
{
    __shared__ float ws[32 * 9 * OCP];
    int p  = blockIdx.x * 128 + threadIdx.x;
    int b  = p / HW, hw = p % HW;
    int h  = hw / Wd, w = hw % Wd;

    float acc[OC];
#pragma unroll
    for (int i = 0; i < OC; i++) acc[i] = 0.f;

    for (int c0 = 0; c0 < CHI; c0 += 32) {
        __syncthreads();
        for (int i = threadIdx.x; i < 32 * 9 * OC; i += 128) {
            int oc = i % OC;
            int ct = i / OC;
            ws[ct * OCP + oc] = w_off[(oc * CHI + c0 + ct / 9) * 9 + (ct % 9)];
        }
        __syncthreads();

        const float* xb = x + ((size_t)b * CHI + c0) * HW;
        for (int cc = 0; cc < 32; cc++) {
            const float* xc = xb + cc * HW;
#pragma unroll
            for (int ty = 0; ty < 3; ty++) {
                int y = h + ty - 1;
                bool yv = ((unsigned)y < (unsigned)Hd);
#pragma unroll
                for (int tx = 0; tx < 3; tx++) {
                    int xx = w + tx - 1;
                    float xv = (yv && (unsigned)xx < (unsigned)Wd) ? xc[y * Wd + xx] : 0.f;
                    const float* wr = &ws[(cc * 9 + ty * 3 + tx) * OCP];
#pragma unroll
                    for (int oc = 0; oc < OC; oc++) acc[oc] += wr[oc] * xv;
                }
            }
        }
    }

#pragma unroll
    for (int k = 0; k < Kt; k++) {
        float dy = acc[2 * k]     + b_off[2 * k];
        float dx = acc[2 * k + 1] + b_off[2 * k + 1];
        float mz = acc[18 + k]    + b_off[18 + k];
        float m  = 1.f / (1.f + expf(-mz));

        float py = dy + (float)(h + k / 3 - 1);
        float px = dx + (float)(w + k % 3 - 1);
        float fy = floorf(py), fx = floorf(px);
        float ly = py - fy,    lx = px - fx;
        int y0 = (int)fy, x0 = (int)fx, y1 = y0 + 1, x1 = x0 + 1;

        float vy0 = ((unsigned)y0 < (unsigned)Hd) ? 1.f : 0.f;
        float vy1 = ((unsigned)y1 < (unsigned)Hd) ? 1.f : 0.f;
        float vx0 = ((unsigned)x0 < (unsigned)Wd) ? 1.f : 0.f;
        float vx1 = ((unsigned)x1 < (unsigned)Wd) ? 1.f : 0.f;

        int y0c = min(max(y0, 0), Hd - 1), y1c = min(max(y1, 0), Hd - 1);
        int x0c = min(max(x0, 0), Wd - 1), x1c = min(max(x1, 0), Wd - 1);

        TapParam tp;
        tp.o00 = y0c * Wd + x0c;  tp.o01 = y0c * Wd + x1c;
        tp.o10 = y1c * Wd + x0c;  tp.o11 = y1c * Wd + x1c;
        tp.w00 = (1.f - ly) * (1.f - lx) * vy0 * vx0 * m;
        tp.w01 = (1.f - ly) * lx         * vy0 * vx1 * m;
        tp.w10 = ly * (1.f - lx)         * vy1 * vx0 * m;
        tp.w11 = ly * lx                 * vy1 * vx1 * m;
        g_params[(b * Kt + k) * HW + hw] = tp;
    }
}

// ---------------------------------------------------------------------------
// Kernel 2: split w_conv into bf16 hi/lo, [CHO][KD] K-major.
// ---------------------------------------------------------------------------
__global__ void __launch_bounds__(256) k_wsplit(const float* __restrict__ w)
{
    int i = blockIdx.x * 256 + threadIdx.x;
    float v = w[i];
    unsigned hb = bf16_rn(v);
    float r = v - __uint_as_float(hb << 16);
    g_wh[i] = (unsigned short)hb;
    g_wl[i] = (unsigned short)bf16_rn(r);
}

// ---------------------------------------------------------------------------
// Kernel 3: deformable im2col -> bf16 hi/lo, K-major [pixel][KD].
// ---------------------------------------------------------------------------
__global__ void __launch_bounds__(256) k_cols(const float* __restrict__ x)
{
    int p  = blockIdx.x * 256 + threadIdx.x;   // grid.x = 144
    int c0 = blockIdx.y * 8;                   // grid.y = 32
    int b  = p / HW, hw = p % HW;
    const float* xb = x + ((size_t)b * CHI + c0) * HW;

    unsigned hbuf[36], lbuf[36];
#pragma unroll
    for (int j = 0; j < 36; j++) { hbuf[j] = 0u; lbuf[j] = 0u; }

#pragma unroll
    for (int k = 0; k < Kt; k++) {
        TapParam tp = g_params[(b * Kt + k) * HW + hw];
#pragma unroll
        for (int cc = 0; cc < 8; cc++) {
            const float* xc = xb + cc * HW;
            float v = tp.w00 * xc[tp.o00] + tp.w01 * xc[tp.o01]
                    + tp.w10 * xc[tp.o10] + tp.w11 * xc[tp.o11];
            unsigned hb = bf16_rn(v);
            float r = v - __uint_as_float(hb << 16);
            unsigned lb = bf16_rn(r);
            int e = cc * 9 + k;
            int sh = (e & 1) * 16;
            hbuf[e >> 1] |= hb << sh;
            lbuf[e >> 1] |= lb << sh;
        }
    }

    uint4* dh = (uint4*)(g_colsh + (size_t)p * KD + c0 * 9);
    uint4* dl = (uint4*)(g_colsl + (size_t)p * KD + c0 * 9);
#pragma unroll
    for (int j = 0; j < 9; j++) {
        dh[j] = make_uint4(hbuf[4*j], hbuf[4*j+1], hbuf[4*j+2], hbuf[4*j+3]);
        dl[j] = make_uint4(lbuf[4*j], lbuf[4*j+1], lbuf[4*j+2], lbuf[4*j+3]);
    }
}

// ---------------------------------------------------------------------------
// Kernel 4: mma.sync (HMMA bf16) GEMM, split-bf16 3-product fp32 accumulation.
// CTA: 128 CHO x 128 pixels. 8 warps, warp tile 64x32. BK=64, 2-stage cp.async.
// smem tile: [128 rows][64 bf16] with SW128 row swizzle (u ^= row&7).
// ---------------------------------------------------------------------------
#define NCHUNK 36
#define TILEB  16384                 // 128 rows x 128 bytes
#define STAGEB (4 * TILEB)           // Ahi Alo Bhi Blo

#define LDM4(R0,R1,R2,R3,ADDR) \
    asm volatile("ldmatrix.sync.aligned.m8n8.x4.shared.b16 {%0,%1,%2,%3}, [%4];" \
                 : "=r"(R0),"=r"(R1),"=r"(R2),"=r"(R3) : "r"(ADDR))

#define MMA(C,A,B0,B1) \
    asm volatile("mma.sync.aligned.m16n8k16.row.col.f32.bf16.bf16.f32 " \
                 "{%0,%1,%2,%3},{%4,%5,%6,%7},{%8,%9},{%0,%1,%2,%3};" \
                 : "+f"((C)[0]),"+f"((C)[1]),"+f"((C)[2]),"+f"((C)[3]) \
                 : "r"((A)[0]),"r"((A)[1]),"r"((A)[2]),"r"((A)[3]),   \
                   "r"(B0),"r"(B1))

__device__ __forceinline__ void load_chunk(unsigned smBase, int stage, int chunk,
                                           int oBase, int pBase, int tid)
{
    unsigned dstBase = smBase + stage * STAGEB;
    int k0 = chunk * 64;
#pragma unroll
    for (int j = 0; j < 16; j++) {
        int i    = tid + j * 256;        // 0..4095
        int tile = i >> 10;              // 0..3
        int row  = (i >> 3) & 127;
        int u    = i & 7;
        const unsigned short* src;
        int rbase;
        if (tile < 2) { src = (tile == 0) ? g_wh   : g_wl;   rbase = oBase; }
        else          { src = (tile == 2) ? g_colsh : g_colsl; rbase = pBase; }
        const char* g = (const char*)src + ((size_t)(rbase + row) * KD + k0) * 2 + u * 16;
        unsigned d = dstBase + tile * TILEB + row * 128 + ((u ^ (row & 7)) * 16);
        asm volatile("cp.async.cg.shared.global [%0], [%1], 16;" :: "r"(d), "l"(g));
    }
    asm volatile("cp.async.commit_group;" ::: "memory");
}

__global__ void __launch_bounds__(256, 1) k_gemm(
    const float* __restrict__ bconv,
    float* __restrict__ out)
{
    extern __shared__ char sm[];
    unsigned smBase = (unsigned)__cvta_generic_to_shared(sm);

    int tid = threadIdx.x, lane = tid & 31, wid = tid >> 5;
    int wm = wid & 1;            // m half (64 rows)
    int wn = wid >> 1;           // n quarter (32 pixels)
    int pBase = blockIdx.x * 128;
    int oBase = blockIdx.y * 128;

    // ldmatrix per-lane geometry
    unsigned aRL = ((lane >> 3) & 1) * 8 + (lane & 7);   // A: row-in-tile16
    unsigned aU  = lane >> 4;                            // A: k8 unit
    unsigned bRL = ((lane >> 4) & 1) * 8 + (lane & 7);   // B: row-in-tile16
    unsigned bU  = (lane >> 3) & 1;                      // B: k8 unit
    unsigned aRowOff[4], bRowOff[2];
#pragma unroll
    for (int mt = 0; mt < 4; mt++) aRowOff[mt] = (wm * 64 + mt * 16 + aRL) * 128;
#pragma unroll
    for (int nt = 0; nt < 2; nt++) bRowOff[nt] = (wn * 32 + nt * 16 + bRL) * 128;
    unsigned aMsk = aRL & 7, bMsk = bRL & 7;

    float c[16][4];
#pragma unroll
    for (int i = 0; i < 16; i++)
#pragma unroll
        for (int j = 0; j < 4; j++) c[i][j] = 0.f;

    load_chunk(smBase, 0, 0, oBase, pBase, tid);

    for (int ch = 0; ch < NCHUNK; ch++) {
        if (ch + 1 < NCHUNK) {
            load_chunk(smBase, (ch + 1) & 1, ch + 1, oBase, pBase, tid);
            asm volatile("cp.async.wait_group 1;" ::: "memory");
        } else {
            asm volatile("cp.async.wait_group 0;" ::: "memory");
        }
        __syncthreads();

        unsigned base = smBase + (ch & 1) * STAGEB;
        unsigned sAh = base, sAl = base + TILEB, sBh = base + 2 * TILEB, sBl = base + 3 * TILEB;

#pragma unroll
        for (int kk = 0; kk < 4; kk++) {
            unsigned ua = ((kk * 2 + aU) ^ aMsk) * 16;
            unsigned ub = ((kk * 2 + bU) ^ bMsk) * 16;

            unsigned ah[4][4], al[4][4], bh[2][4], bl[2][4];
#pragma unroll
            for (int mt = 0; mt < 4; mt++) {
                LDM4(ah[mt][0], ah[mt][1], ah[mt][2], ah[mt][3], sAh + aRowOff[mt] + ua);
                LDM4(al[mt][0], al[mt][1], al[mt][2], al[mt][3], sAl + aRowOff[mt] + ua);
            }
#pragma unroll
            for (int nt = 0; nt < 2; nt++) {
                LDM4(bh[nt][0], bh[nt][1], bh[nt][2], bh[nt][3], sBh + bRowOff[nt] + ub);
                LDM4(bl[nt][0], bl[nt][1], bl[nt][2], bl[nt][3], sBl + bRowOff[nt] + ub);
            }

            // a-frag regs: r0,r1 = k0-7/k8-15 row l/4 & +8; mma A order {r0,r1,r2,r3}
            // but fragment order is {m0-7 k0-7},{m8-15 k0-7},{m0-7 k8-15},{m8-15 k8-15}
#pragma unroll
            for (int mt = 0; mt < 4; mt++)
#pragma unroll
                for (int nt = 0; nt < 4; nt++) {
                    int n2 = nt >> 1, jj = (nt & 1) * 2;
                    float* cc = c[mt * 4 + nt];
                    MMA(cc, ah[mt], bh[n2][jj], bh[n2][jj + 1]);
                    MMA(cc, ah[mt], bl[n2][jj], bl[n2][jj + 1]);
                    MMA(cc, al[mt], bh[n2][jj], bh[n2][jj + 1]);
                }
        }
        __syncthreads();
    }

    // Epilogue: + bias, NCHW stores (pixel tile stays inside one batch image).
    int b = pBase / HW, hwB = pBase % HW;
#pragma unroll
    for (int mt = 0; mt < 4; mt++) {
        int o = oBase + wm * 64 + mt * 16 + (lane >> 2);
        float bias0 = bconv[o], bias8 = bconv[o + 8];
        float* r0p = out + ((size_t)b * CHO + o) * HW + hwB;
        float* r8p = r0p + 8 * HW;
#pragma unroll
        for (int nt = 0; nt < 4; nt++) {
            int p = wn * 32 + nt * 8 + (lane & 3) * 2;
            float2 v0 = make_float2(c[mt * 4 + nt][0] + bias0, c[mt * 4 + nt][1] + bias0);
            float2 v1 = make_float2(c[mt * 4 + nt][2] + bias8, c[mt * 4 + nt][3] + bias8);
            *(float2*)(r0p + p) = v0;
            *(float2*)(r8p + p) = v1;
        }
    }
}

// ---------------------------------------------------------------------------
// Kernel 5/6: BN stats + apply.
// ---------------------------------------------------------------------------
__global__ void __launch_bounds__(256) k_bnstats(const float* __restrict__ out)
{
    __shared__ float ss[256], ss2[256];
    int o = blockIdx.x;
    float s = 0.f, s2 = 0.f;
    for (int i = threadIdx.x; i < Bn * HW; i += 256) {
        int b = i / HW;
        float v = out[((size_t)b * CHO + o) * HW + (i % HW)];
        s += v; s2 += v * v;
    }
    ss[threadIdx.x] = s; ss2[threadIdx.x] = s2;
    __syncthreads();
    for (int st = 128; st > 0; st >>= 1) {
        if (threadIdx.x < st) {
            ss[threadIdx.x]  += ss[threadIdx.x + st];
            ss2[threadIdx.x] += ss2[threadIdx.x + st];
        }
        __syncthreads();
    }
    if (threadIdx.x == 0) {
        float inv_n = 1.f / (float)(Bn * HW);
        float mean = ss[0] * inv_n;
        float var  = ss2[0] * inv_n - mean * mean;
        g_stats[o]       = mean;
        g_stats[CHO + o] = rsqrtf(var + BN_EPS);
    }
}

__global__ void __launch_bounds__(256) k_bnapply(
    float* __restrict__ out,
    const float* __restrict__ gamma,
    const float* __restrict__ beta)
{
    int i = blockIdx.x * 256 + threadIdx.x;
    int o = (i / HW) & (CHO - 1);
    float v = out[i];
    float y = gamma[o] * ((v - g_stats[o]) * g_stats[CHO + o]) + beta[o];
    out[i] = fmaxf(y, 0.f);
}

// ---------------------------------------------------------------------------
extern "C" void kernel_launch(void* const* d_in, const int* in_sizes, int n_in,
                              void* d_out, int out_size)
{
    const float* x      = (const float*)d_in[0];
    const float* w_off  = (const float*)d_in[1];
    const float* b_off  = (const float*)d_in[2];
    const float* w_conv = (const float*)d_in[3];
    const float* b_conv = (const float*)d_in[4];
    const float* gamma  = (const float*)d_in[5];
    const float* beta   = (const float*)d_in[6];
    float* out = (float*)d_out;

    cudaFuncSetAttribute(k_gemm, cudaFuncAttributeMaxDynamicSharedMemorySize,
                         2 * STAGEB);

    k_offset<<<Mpx / 128, 128>>>(x, w_off, b_off);
    k_wsplit<<<(CHO * KD) / 256, 256>>>(w_conv);

    dim3 gcols(Mpx / 256, CHI / 8);
    k_cols<<<gcols, 256>>>(x);

    dim3 ggemm(Mpx / 128, CHO / 128);
    k_gemm<<<ggemm, 256, 2 * STAGEB>>>(b_conv, out);

    k_bnstats<<<CHO, 256>>>(out);
    k_bnapply<<<(size_t)Bn * CHO * HW / 256, 256>>>(out, gamma, beta);
}